// round 14
// baseline (speedup 1.0000x reference)
#include <cuda_runtime.h>
#include <cuda_fp16.h>
#include <cstdint>
#include <math.h>

// ---------------------------------------------------------------------------
// DLRM forward, 4 launches:
//   prep -> bottom_mlp (fused 3-layer) -> interact -> top_mlp (fused 3-layer)
// mma.sync m16n8k16 fp16 (fp32 accum). 1024 threads / 32 warps per CTA.
// Streamed stages: warp-private cp.async pipeline (warp w streams only its
// NW = NOUT/32 weight rows; no CTA barriers in the steady-state loop).
// ---------------------------------------------------------------------------

#define BATCH   4096
#define MDEN    13
#define NI      27
#define EMBD    64
#define VOCAB   100000
#define TOPIN   415
#define PDIM    512

// fp16 P buffer (cols 0:64 = x_bot, 64:415 = pair dots, 415:512 = 0)
__device__ __align__(16) __half g_ph[BATCH * PDIM];

// fp16 weights
#define HW0   0                     // [512,32]  (bw0 zero-padded 13->32)
#define HW1   (HW0  + 512*32)       // [256,512]
#define HW2   (HW1  + 256*512)      // [64,256]
#define HTW0  (HW2  + 64*256)       // [512,512] (tw0 zero-padded 415->512)
#define HTW1  (HTW0 + 512*512)      // [256,512]
#define HTOTAL (HTW1 + 256*512)
__device__ __align__(16) __half g_wh[HTOTAL];

#define BROW    40                  // halves per smem weight row (32 + 8 pad)
#define BUFH    (512*BROW)          // halves per weight buffer

__device__ __forceinline__ uint32_t smem_u32(const void* p) {
    uint32_t a;
    asm("{ .reg .u64 t; cvta.to.shared.u64 t, %1; cvt.u32.u64 %0, t; }"
        : "=r"(a) : "l"(p));
    return a;
}
__device__ __forceinline__ void mma_f16(float* c, const uint32_t* a,
                                        uint32_t b0, uint32_t b1) {
    asm volatile(
        "mma.sync.aligned.m16n8k16.row.col.f32.f16.f16.f32 "
        "{%0,%1,%2,%3}, {%4,%5,%6,%7}, {%8,%9}, {%0,%1,%2,%3};"
        : "+f"(c[0]), "+f"(c[1]), "+f"(c[2]), "+f"(c[3])
        : "r"(a[0]), "r"(a[1]), "r"(a[2]), "r"(a[3]), "r"(b0), "r"(b1));
}
__device__ __forceinline__ void ldm_x4(uint32_t* r, uint32_t addr) {
    asm volatile("ldmatrix.sync.aligned.m8n8.x4.shared.b16 {%0,%1,%2,%3}, [%4];"
                 : "=r"(r[0]), "=r"(r[1]), "=r"(r[2]), "=r"(r[3]) : "r"(addr));
}
__device__ __forceinline__ void ldm_x2(uint32_t* r, uint32_t addr) {
    asm volatile("ldmatrix.sync.aligned.m8n8.x2.shared.b16 {%0,%1}, [%2];"
                 : "=r"(r[0]), "=r"(r[1]) : "r"(addr));
}
__device__ __forceinline__ void cp16(uint32_t saddr, const void* g) {
    asm volatile("cp.async.cg.shared.global [%0], [%1], 16;" :: "r"(saddr), "l"(g));
}
#define CP_COMMIT() asm volatile("cp.async.commit_group;" ::: "memory")

// ---------------------------------------------------------------------------
// Prep
// ---------------------------------------------------------------------------
__global__ void prep_kernel(const float* __restrict__ bw0,
                            const float* __restrict__ bw1,
                            const float* __restrict__ bw2,
                            const float* __restrict__ tw0,
                            const float* __restrict__ tw1)
{
    int tid = blockIdx.x * blockDim.x + threadIdx.x;
    int stride = gridDim.x * blockDim.x;

    for (int i = tid; i < 512 * 32; i += stride) {
        int r = i >> 5, c = i & 31;
        g_wh[HW0 + i] = __float2half_rn((c < MDEN) ? bw0[r * MDEN + c] : 0.f);
    }
    for (int i = tid; i < 256 * 512; i += stride)
        g_wh[HW1 + i] = __float2half_rn(bw1[i]);
    for (int i = tid; i < 64 * 256; i += stride)
        g_wh[HW2 + i] = __float2half_rn(bw2[i]);
    for (int i = tid; i < 512 * 512; i += stride) {
        int r = i >> 9, c = i & 511;
        g_wh[HTW0 + i] = __float2half_rn((c < TOPIN) ? tw0[r * TOPIN + c] : 0.f);
    }
    for (int i = tid; i < 256 * 512; i += stride)
        g_wh[HTW1 + i] = __float2half_rn(tw1[i]);
    for (int i = tid; i < BATCH * (PDIM - TOPIN); i += stride) {
        int r = i / (PDIM - TOPIN), c = TOPIN + i % (PDIM - TOPIN);
        g_ph[(size_t)r * PDIM + c] = __float2half_rn(0.f);
    }
}

// ---------------------------------------------------------------------------
// MLP stage (1024 threads / 32 warps):
//   Ds[32][NOUT] = relu( As[32][K_TOT] @ W[NOUT,K_TOT]^T + bias )
// Warp w owns n-cols [w*NW, (w+1)*NW), NW = NOUT/32 (16 or 8), full m=32.
// RESIDENT: weights already in Wc buffer 0 (no streaming).
// Streamed: warp-private cp.async pipeline (warp loads ONLY its own NW rows
// of each [NOUT x 32k] chunk; 3 buffers, 2 chunks in flight, no barriers).
// ---------------------------------------------------------------------------
template<int K_TOT, int NOUT, int ASTRIDE, int DSTRIDE, bool RESIDENT>
__device__ __forceinline__ void mlp_stage(
    const __half* As, __half* Wc, const __half* Wg,
    const float* bias, __half* Ds)
{
    constexpr int NC  = K_TOT / 32;
    constexpr int NW  = NOUT / 32;    // n-cols per warp (16 or 8)
    constexpr int NT  = NW / 8;       // n8 tiles per warp (2 or 1)
    constexpr int CPI = NW / 8;       // cp16 per thread per chunk (2 or 1)
    static_assert(NW == 16 || NW == 8, "NW");

    const int tid  = threadIdx.x;
    const int lane = tid & 31, wid = tid >> 5;
    const int qr   = lane & 3, gr = lane >> 2;
    const int lrow = lane & 15, lkof = (lane >> 4) << 3;
    const int lb   = lane & 7,  sel  = lane >> 3;
    const int bko  = (NT == 2) ? ((sel & 1) << 3) : (((lane >> 3) & 1) << 3);
    const int brow = (NT == 2) ? (wid * NW + ((sel & 2) << 2) + lb)
                               : (wid * NW + lb);

    // warp-private slice: rows [wid*NW, (wid+1)*NW) of each chunk
    auto issue = [&](int g) {
        const __half* src = Wg + g * 32;
        __half* buf = Wc + (g % 3) * BUFH;
        #pragma unroll
        for (int j = 0; j < CPI; j++) {
            int f = j * 32 + lane;
            int r = wid * NW + (f >> 2);        // row within chunk
            int c = (f & 3) * 8;                // halves offset within 64B row
            cp16(smem_u32(buf + r * BROW + c), src + (size_t)r * K_TOT + c);
        }
        CP_COMMIT();
    };

    if (!RESIDENT) {
        issue(0);
        if (NC > 1) issue(1);
    }

    float acc[2][NT][4];
    #pragma unroll
    for (int mt = 0; mt < 2; mt++)
        #pragma unroll
        for (int j = 0; j < NT; j++)
            #pragma unroll
            for (int e = 0; e < 4; e++)
                acc[mt][j][e] = 0.f;

    #pragma unroll 1
    for (int g = 0; g < NC; g++) {
        if (!RESIDENT) {
            if (g < NC - 1) asm volatile("cp.async.wait_group 1;" ::: "memory");
            else            asm volatile("cp.async.wait_group 0;" ::: "memory");
            // no __syncthreads: buffers are warp-private slices
        }
        const __half* Wb = Wc + (RESIDENT ? 0 : (g % 3)) * BUFH;

        #pragma unroll
        for (int kk = 0; kk < 32; kk += 16) {
            uint32_t a0[4], a1[4];
            ldm_x4(a0, smem_u32(As + (size_t)lrow * ASTRIDE + g * 32 + kk + lkof));
            ldm_x4(a1, smem_u32(As + (size_t)(16 + lrow) * ASTRIDE + g * 32 + kk + lkof));
            if (NT == 2) {
                uint32_t bf[4];
                ldm_x4(bf, smem_u32(Wb + (size_t)brow * BROW + kk + bko));
                mma_f16(acc[0][0], a0, bf[0], bf[1]);
                mma_f16(acc[0][NT-1], a0, bf[2], bf[3]);
                mma_f16(acc[1][0], a1, bf[0], bf[1]);
                mma_f16(acc[1][NT-1], a1, bf[2], bf[3]);
            } else {
                uint32_t bf[2];
                ldm_x2(bf, smem_u32(Wb + (size_t)brow * BROW + kk + bko));
                mma_f16(acc[0][0], a0, bf[0], bf[1]);
                mma_f16(acc[1][0], a1, bf[0], bf[1]);
            }
        }

        if (!RESIDENT && g + 2 < NC) issue(g + 2);
    }

    // epilogue: bias + relu -> Ds (fp16)
    #pragma unroll
    for (int mt = 0; mt < 2; mt++) {
        #pragma unroll
        for (int j = 0; j < NT; j++) {
            int col = wid * NW + j * 8 + 2 * qr;
            float bx = bias[col], by = bias[col + 1];
            float v0 = fmaxf(acc[mt][j][0] + bx, 0.f), v1 = fmaxf(acc[mt][j][1] + by, 0.f);
            float v2 = fmaxf(acc[mt][j][2] + bx, 0.f), v3 = fmaxf(acc[mt][j][3] + by, 0.f);
            int r0 = mt * 16 + gr;
            *(__half2*)&Ds[(size_t)r0 * DSTRIDE + col]       = __floats2half2_rn(v0, v1);
            *(__half2*)&Ds[(size_t)(r0 + 8) * DSTRIDE + col] = __floats2half2_rn(v2, v3);
        }
    }
}

// ---------------------------------------------------------------------------
// Bottom MLP megakernel: 32 batch rows / CTA, grid 128, 1024 threads.
// ---------------------------------------------------------------------------
#define BOT_SMEM 209408
__global__ __launch_bounds__(1024)
void bottom_mlp(const float* __restrict__ dense_x,
                const __half* __restrict__ W0h,
                const __half* __restrict__ W1h,
                const __half* __restrict__ W2h,
                const float* __restrict__ bb0,
                const float* __restrict__ bb1,
                const float* __restrict__ bb2)
{
    extern __shared__ __align__(16) char smem[];
    __half (*Xs)[40]   = (__half(*)[40] )(smem + 0);        //   2560 B
    __half (*H1s)[520] = (__half(*)[520])(smem + 2560);     //  33280 B
    __half* Wc         = (__half*)       (smem + 35840);    // 122880 B (3 bufs)
    __half (*H2s)[264] = (__half(*)[264])(smem + 158720);   //  16896 B
    __half (*W2s)[264] = (__half(*)[264])(smem + 175616);   //  33792 B

    const int tid  = threadIdx.x;
    const int lane = tid & 31, wid = tid >> 5;
    const int qr   = lane & 3, gr = lane >> 2;
    const int lrow = lane & 15, lkof = (lane >> 4) << 3;
    const int lb   = lane & 7;
    const int m0   = blockIdx.x * 32;

    // ---- loads: Xs (padded), W0 -> Wc buffer 0 (cp.async), W2s ----
    for (int i = tid; i < 32 * MDEN; i += 1024) {
        int r = i / MDEN, c = i % MDEN;
        Xs[r][c] = __float2half_rn(dense_x[(size_t)(m0 + r) * MDEN + c]);
    }
    for (int i = tid; i < 32 * (32 - MDEN); i += 1024) {
        int r = i / (32 - MDEN), c = MDEN + i % (32 - MDEN);
        Xs[r][c] = __float2half_rn(0.f);
    }
    #pragma unroll
    for (int j = 0; j < 2; j++) {                    // W0: 512 rows x 32 k
        int f = tid + j * 1024, r = f >> 2, c = (f & 3) * 8;
        cp16(smem_u32(Wc + r * BROW + c), W0h + r * 32 + c);
    }
    CP_COMMIT();
    #pragma unroll
    for (int j = 0; j < 2; j++) {                    // W2s: 64x256 halves
        int f = tid + j * 1024, r = f >> 5, c = (f & 31) * 8;
        *(uint4*)&W2s[r][c] = *(const uint4*)&W2h[r * 256 + c];
    }
    asm volatile("cp.async.wait_group 0;" ::: "memory");
    __syncthreads();

    // ---- stage A: K=32 resident, out 32x512 -> H1s (relu) ----
    mlp_stage<32, 512, 40, 520, true>(&Xs[0][0], Wc, nullptr, bb0, &H1s[0][0]);
    __syncthreads();

    // ---- stage B: K=512 streamed (warp-private), out 32x256 -> H2s (relu) ----
    mlp_stage<512, 256, 520, 264, false>(&H1s[0][0], Wc, W1h, bb1, &H2s[0][0]);
    __syncthreads();

    // ---- stage C: K=256, out 32x64 -> P[:,0:64] fp16 (warps 0-15, resident) ----
    if (wid < 16) {
        const int wm0 = (wid >> 3) * 16, wng = wid & 7;
        float acc[4];
        #pragma unroll
        for (int e = 0; e < 4; e++) acc[e] = 0.f;
        const int sel1 = (lane >> 3) & 1;
        #pragma unroll 4
        for (int kk = 0; kk < 256; kk += 16) {
            uint32_t af[4], bf[2];
            ldm_x4(af, smem_u32(&H2s[wm0 + lrow][kk + lkof]));
            ldm_x2(bf, smem_u32(&W2s[wng * 8 + lb][kk + sel1 * 8]));
            mma_f16(acc, af, bf[0], bf[1]);
        }
        int col = wng * 8 + 2 * qr;
        float bx = bb2[col], by = bb2[col + 1];
        __half2 v0 = __floats2half2_rn(acc[0] + bx, acc[1] + by);
        __half2 v1 = __floats2half2_rn(acc[2] + bx, acc[3] + by);
        *(__half2*)&g_ph[(size_t)(m0 + wm0 + gr) * PDIM + col]     = v0;
        *(__half2*)&g_ph[(size_t)(m0 + wm0 + gr + 8) * PDIM + col] = v1;
    }
}

// ---------------------------------------------------------------------------
// Top MLP megakernel: 32 batch rows / CTA, grid 128, 1024 threads.
// ---------------------------------------------------------------------------
#define TOP_SMEM 206336
__global__ __launch_bounds__(1024)
void top_mlp(const __half* __restrict__ TW0h,
             const __half* __restrict__ TW1h,
             const float* __restrict__ tb0,
             const float* __restrict__ tb1,
             const float* __restrict__ tw2,
             const float* __restrict__ tb2,
             float* __restrict__ out)
{
    extern __shared__ __align__(16) char smem[];
    __half (*Xs)[520]  = (__half(*)[520])(smem + 0);        //  33280 B
    __half (*H1s)[520] = (__half(*)[520])(smem + 33280);    //  33280 B
    __half* Wc         = (__half*)       (smem + 66560);    // 122880 B (3 bufs)
    __half (*H2s)[264] = (__half(*)[264])(smem + 189440);   //  16896 B

    const int tid = threadIdx.x;
    const int m0  = blockIdx.x * 32;

    // load P rows (fp16): 32 rows x 512 halves = 32KB
    const __half* Pr = g_ph + (size_t)m0 * PDIM;
    #pragma unroll
    for (int j = 0; j < 2; j++) {
        int f = tid + j * 1024, r = f >> 6, cq = f & 63;
        *(uint4*)&Xs[r][cq * 8] = *(const uint4*)&Pr[(size_t)r * PDIM + cq * 8];
    }
    __syncthreads();

    mlp_stage<512, 512, 520, 520, false>(&Xs[0][0], Wc, TW0h, tb0, &H1s[0][0]);
    __syncthreads();
    mlp_stage<512, 256, 520, 264, false>(&H1s[0][0], Wc, TW1h, tb1, &H2s[0][0]);
    __syncthreads();

    // final dot: 32 lanes per row (H2s already holds relu(T2))
    {
        int r = tid >> 5, lane = tid & 31;
        float s = 0.f;
        #pragma unroll
        for (int c = 0; c < 8; c++) {
            int col = lane * 8 + c;
            s += __half2float(H2s[r][col]) * tw2[col];
        }
        s += __shfl_xor_sync(0xffffffffu, s, 1);
        s += __shfl_xor_sync(0xffffffffu, s, 2);
        s += __shfl_xor_sync(0xffffffffu, s, 4);
        s += __shfl_xor_sync(0xffffffffu, s, 8);
        s += __shfl_xor_sync(0xffffffffu, s, 16);
        if (lane == 0) out[m0 + r] = s + tb2[0];
    }
}

// ---------------------------------------------------------------------------
// Interaction kernel. One warp per batch row; x_bot already in P[b][0:64] (fp16).
// ---------------------------------------------------------------------------
#define IPAD 28

__global__ __launch_bounds__(128)
void interact_kernel(const int* __restrict__ sidx,
                     const float* __restrict__ emb)
{
    __shared__ __align__(16) float Tt[4][EMBD][IPAD];

    const int w    = threadIdx.x >> 5;
    const int lane = threadIdx.x & 31;
    const int b    = blockIdx.x * 4 + w;

    __half* prow = g_ph + (size_t)b * PDIM;
    float (*T)[IPAD] = Tt[w];

    // x_bot (fp16 -> fp32)
    {
        __half2 h = ((const __half2*)prow)[lane];
        float2 xb = __half22float2(h);
        T[2*lane    ][0] = xb.x;
        T[2*lane + 1][0] = xb.y;
    }

    const float* srcs[NI - 1];
    #pragma unroll
    for (int r = 0; r < NI - 1; r++) {
        int ix = sidx[(size_t)r * BATCH + b];
        ix = ix < 0 ? 0 : (ix >= VOCAB ? VOCAB - 1 : ix);
        srcs[r] = emb + ((size_t)r * VOCAB + (size_t)ix) * EMBD;
    }
    float2 vbuf[NI - 1];
    #pragma unroll
    for (int r = 0; r < NI - 1; r++)
        vbuf[r] = ((const float2*)srcs[r])[lane];
    #pragma unroll
    for (int r = 0; r < NI - 1; r++) {
        T[2*lane    ][r + 1] = vbuf[r].x;
        T[2*lane + 1][r + 1] = vbuf[r].y;
    }
    __syncwarp();

    if (lane < 28) {
        int ti = 0;
        while ((ti + 1) * (ti + 2) / 2 <= lane) ti++;
        int tj = lane - ti * (ti + 1) / 2;

        float acc[4][4];
        #pragma unroll
        for (int a = 0; a < 4; a++)
            #pragma unroll
            for (int c = 0; c < 4; c++)
                acc[a][c] = 0.f;

        #pragma unroll 8
        for (int k = 0; k < EMBD; k++) {
            float4 av = *(const float4*)&T[k][4*ti];
            float4 bv = *(const float4*)&T[k][4*tj];
            float ra[4] = {av.x, av.y, av.z, av.w};
            float rb[4] = {bv.x, bv.y, bv.z, bv.w};
            #pragma unroll
            for (int a = 0; a < 4; a++)
                #pragma unroll
                for (int c = 0; c < 4; c++)
                    acc[a][c] += ra[a] * rb[c];
        }

        #pragma unroll
        for (int a = 0; a < 4; a++) {
            int i = 4*ti + a;
            #pragma unroll
            for (int c = 0; c < 4; c++) {
                int j = 4*tj + c;
                if (i < NI && j < i)
                    prow[EMBD + i*(i-1)/2 + j] = __float2half_rn(acc[a][c]);
            }
        }
    }
}

// ---------------------------------------------------------------------------
// Launch sequence
// ---------------------------------------------------------------------------
extern "C" void kernel_launch(void* const* d_in, const int* in_sizes, int n_in,
                              void* d_out, int out_size)
{
    const float* dense_x = (const float*)d_in[0];
    const int*   sidx    = (const int*)d_in[1];
    const float* emb     = (const float*)d_in[2];
    const float* bw0 = (const float*)d_in[3];
    const float* bb0 = (const float*)d_in[4];
    const float* bw1 = (const float*)d_in[5];
    const float* bb1 = (const float*)d_in[6];
    const float* bw2 = (const float*)d_in[7];
    const float* bb2 = (const float*)d_in[8];
    const float* tw0 = (const float*)d_in[9];
    const float* tb0 = (const float*)d_in[10];
    const float* tw1 = (const float*)d_in[11];
    const float* tb1 = (const float*)d_in[12];
    const float* tw2 = (const float*)d_in[13];
    const float* tb2 = (const float*)d_in[14];
    float* out = (float*)d_out;

    __half* wh;
    cudaGetSymbolAddress((void**)&wh, g_wh);

    cudaFuncSetAttribute(bottom_mlp, cudaFuncAttributeMaxDynamicSharedMemorySize, BOT_SMEM);
    cudaFuncSetAttribute(top_mlp,    cudaFuncAttributeMaxDynamicSharedMemorySize, TOP_SMEM);

    prep_kernel<<<256, 256>>>(bw0, bw1, bw2, tw0, tw1);

    bottom_mlp<<<BATCH/32, 1024, BOT_SMEM>>>(dense_x, wh + HW0, wh + HW1, wh + HW2,
                                             bb0, bb1, bb2);

    interact_kernel<<<BATCH/4, 128>>>(sidx, emb);

    top_mlp<<<BATCH/32, 1024, TOP_SMEM>>>(wh + HTW0, wh + HTW1,
                                          tb0, tb1, tw2, tb2, out);
}

// round 15
// speedup vs baseline: 1.0756x; 1.0756x over previous
#include <cuda_runtime.h>
#include <cuda_fp16.h>
#include <cstdint>
#include <math.h>

// ---------------------------------------------------------------------------
// DLRM forward, 3 launches:
//   prep -> bottom_mlp (fused 3-layer) -> top_mlp (gather+interact+3-layer)
// mma.sync m16n8k16 fp16 (fp32 accum). 512 threads / 16 warps per CTA.
// Streamed stages: warp-private cp.async pipeline (no CTA barriers in loop).
// ---------------------------------------------------------------------------

#define BATCH   4096
#define MDEN    13
#define NI      27
#define EMBD    64
#define VOCAB   100000
#define TOPIN   415
#define PDIM    512

// compact bottom output: x_bot fp16 [4096, 64]
__device__ __align__(16) __half g_xb[BATCH * EMBD];

// fp16 weights
#define HW0   0                     // [512,32]  (bw0 zero-padded 13->32)
#define HW1   (HW0  + 512*32)       // [256,512]
#define HW2   (HW1  + 256*512)      // [64,256]
#define HTW0  (HW2  + 64*256)       // [512,512] (tw0 zero-padded 415->512)
#define HTW1  (HTW0 + 512*512)      // [256,512]
#define HTOTAL (HTW1 + 256*512)
__device__ __align__(16) __half g_wh[HTOTAL];

#define BROW    40                  // halves per smem weight row (32 + 8 pad)
#define BUFH    (512*BROW)          // halves per weight buffer

__device__ __forceinline__ uint32_t smem_u32(const void* p) {
    uint32_t a;
    asm("{ .reg .u64 t; cvta.to.shared.u64 t, %1; cvt.u32.u64 %0, t; }"
        : "=r"(a) : "l"(p));
    return a;
}
__device__ __forceinline__ void mma_f16(float* c, const uint32_t* a,
                                        uint32_t b0, uint32_t b1) {
    asm volatile(
        "mma.sync.aligned.m16n8k16.row.col.f32.f16.f16.f32 "
        "{%0,%1,%2,%3}, {%4,%5,%6,%7}, {%8,%9}, {%0,%1,%2,%3};"
        : "+f"(c[0]), "+f"(c[1]), "+f"(c[2]), "+f"(c[3])
        : "r"(a[0]), "r"(a[1]), "r"(a[2]), "r"(a[3]), "r"(b0), "r"(b1));
}
__device__ __forceinline__ void ldm_x4(uint32_t* r, uint32_t addr) {
    asm volatile("ldmatrix.sync.aligned.m8n8.x4.shared.b16 {%0,%1,%2,%3}, [%4];"
                 : "=r"(r[0]), "=r"(r[1]), "=r"(r[2]), "=r"(r[3]) : "r"(addr));
}
__device__ __forceinline__ void ldm_x2(uint32_t* r, uint32_t addr) {
    asm volatile("ldmatrix.sync.aligned.m8n8.x2.shared.b16 {%0,%1}, [%2];"
                 : "=r"(r[0]), "=r"(r[1]) : "r"(addr));
}
__device__ __forceinline__ void cp16(uint32_t saddr, const void* g) {
    asm volatile("cp.async.cg.shared.global [%0], [%1], 16;" :: "r"(saddr), "l"(g));
}
#define CP_COMMIT() asm volatile("cp.async.commit_group;" ::: "memory")

// ---------------------------------------------------------------------------
// Prep: convert/pad weights to fp16.
// ---------------------------------------------------------------------------
__global__ void prep_kernel(const float* __restrict__ bw0,
                            const float* __restrict__ bw1,
                            const float* __restrict__ bw2,
                            const float* __restrict__ tw0,
                            const float* __restrict__ tw1)
{
    int tid = blockIdx.x * blockDim.x + threadIdx.x;
    int stride = gridDim.x * blockDim.x;

    for (int i = tid; i < 512 * 32; i += stride) {
        int r = i >> 5, c = i & 31;
        g_wh[HW0 + i] = __float2half_rn((c < MDEN) ? bw0[r * MDEN + c] : 0.f);
    }
    for (int i = tid; i < 256 * 512; i += stride)
        g_wh[HW1 + i] = __float2half_rn(bw1[i]);
    for (int i = tid; i < 64 * 256; i += stride)
        g_wh[HW2 + i] = __float2half_rn(bw2[i]);
    for (int i = tid; i < 512 * 512; i += stride) {
        int r = i >> 9, c = i & 511;
        g_wh[HTW0 + i] = __float2half_rn((c < TOPIN) ? tw0[r * TOPIN + c] : 0.f);
    }
    for (int i = tid; i < 256 * 512; i += stride)
        g_wh[HTW1 + i] = __float2half_rn(tw1[i]);
}

// ---------------------------------------------------------------------------
// MLP stage (512 threads / 16 warps):
//   Ds[32][NOUT] = relu( As[32][K_TOT] @ W[NOUT,K_TOT]^T + bias )
// Warp w owns n-cols [w*NW, (w+1)*NW), NW = NOUT/16, full m=32.
// RESIDENT: weights already in Wc buffer 0. Streamed: warp-private cp.async
// pipeline (each warp loads only its own NW rows of each [NOUT x 32k] chunk;
// 3 buffers, 2 chunks in flight, no __syncthreads in the loop).
// ---------------------------------------------------------------------------
template<int K_TOT, int NOUT, int ASTRIDE, int DSTRIDE, bool RESIDENT>
__device__ __forceinline__ void mlp_stage(
    const __half* As, __half* Wc, const __half* Wg,
    const float* bias, __half* Ds)
{
    constexpr int NC = K_TOT / 32;
    constexpr int NW = NOUT / 16;     // n-cols per warp (16 or 32)
    constexpr int NT = NW / 8;        // n8 tiles per warp (2 or 4)
    constexpr int NP = (NW + 15) / 16;// ldm_x4 B loads per kstep (1 or 2)
    constexpr int CPI = NW / 8;       // cp16 per thread per chunk

    const int tid  = threadIdx.x;
    const int lane = tid & 31, wid = tid >> 5;
    const int qr   = lane & 3, gr = lane >> 2;
    const int lrow = lane & 15, lkof = (lane >> 4) << 3;
    const int lb   = lane & 7,  sel  = lane >> 3;
    const int bko  = (sel & 1) << 3;
    const int brow = wid * NW + ((sel & 2) << 2) + lb;

    auto issue = [&](int g) {
        const __half* src = Wg + g * 32;
        __half* buf = Wc + (g % 3) * BUFH;
        #pragma unroll
        for (int j = 0; j < CPI; j++) {
            int f = j * 32 + lane;
            int r = wid * NW + (f >> 2);
            int c = (f & 3) * 8;
            cp16(smem_u32(buf + r * BROW + c), src + (size_t)r * K_TOT + c);
        }
        CP_COMMIT();
    };

    if (!RESIDENT) {
        issue(0);
        if (NC > 1) issue(1);
    }

    float acc[2][NT][4];
    #pragma unroll
    for (int mt = 0; mt < 2; mt++)
        #pragma unroll
        for (int j = 0; j < NT; j++)
            #pragma unroll
            for (int e = 0; e < 4; e++)
                acc[mt][j][e] = 0.f;

    #pragma unroll 1
    for (int g = 0; g < NC; g++) {
        if (!RESIDENT) {
            if (g < NC - 1) asm volatile("cp.async.wait_group 1;" ::: "memory");
            else            asm volatile("cp.async.wait_group 0;" ::: "memory");
        }
        const __half* Wb = Wc + (RESIDENT ? 0 : (g % 3)) * BUFH;

        #pragma unroll
        for (int kk = 0; kk < 32; kk += 16) {
            uint32_t a0[4], a1[4];
            ldm_x4(a0, smem_u32(As + (size_t)lrow * ASTRIDE + g * 32 + kk + lkof));
            ldm_x4(a1, smem_u32(As + (size_t)(16 + lrow) * ASTRIDE + g * 32 + kk + lkof));
            #pragma unroll
            for (int p = 0; p < NP; p++) {
                uint32_t bf[4];
                ldm_x4(bf, smem_u32(Wb + (size_t)(brow + p * 16) * BROW + kk + bko));
                mma_f16(acc[0][2*p + 0], a0, bf[0], bf[1]);
                mma_f16(acc[0][2*p + 1], a0, bf[2], bf[3]);
                mma_f16(acc[1][2*p + 0], a1, bf[0], bf[1]);
                mma_f16(acc[1][2*p + 1], a1, bf[2], bf[3]);
            }
        }

        if (!RESIDENT && g + 2 < NC) issue(g + 2);
    }

    // epilogue: bias + relu -> Ds (fp16)
    #pragma unroll
    for (int mt = 0; mt < 2; mt++) {
        #pragma unroll
        for (int j = 0; j < NT; j++) {
            int col = wid * NW + j * 8 + 2 * qr;
            float bx = bias[col], by = bias[col + 1];
            float v0 = fmaxf(acc[mt][j][0] + bx, 0.f), v1 = fmaxf(acc[mt][j][1] + by, 0.f);
            float v2 = fmaxf(acc[mt][j][2] + bx, 0.f), v3 = fmaxf(acc[mt][j][3] + by, 0.f);
            int r0 = mt * 16 + gr;
            *(__half2*)&Ds[(size_t)r0 * DSTRIDE + col]       = __floats2half2_rn(v0, v1);
            *(__half2*)&Ds[(size_t)(r0 + 8) * DSTRIDE + col] = __floats2half2_rn(v2, v3);
        }
    }
}

// ---------------------------------------------------------------------------
// Bottom MLP megakernel: 32 batch rows / CTA, grid 128, 512 threads.
//   A: H1 = relu(dense @ W0^T)   B: H2 = relu(H1 @ W1^T)   C: x_bot -> g_xb
// ---------------------------------------------------------------------------
#define BOT_SMEM 209408
__global__ __launch_bounds__(512)
void bottom_mlp(const float* __restrict__ dense_x,
                const __half* __restrict__ W0h,
                const __half* __restrict__ W1h,
                const __half* __restrict__ W2h,
                const float* __restrict__ bb0,
                const float* __restrict__ bb1,
                const float* __restrict__ bb2)
{
    extern __shared__ __align__(16) char smem[];
    __half (*Xs)[40]   = (__half(*)[40] )(smem + 0);        //   2560 B
    __half (*H1s)[520] = (__half(*)[520])(smem + 2560);     //  33280 B
    __half* Wc         = (__half*)       (smem + 35840);    // 122880 B (3 bufs)
    __half (*H2s)[264] = (__half(*)[264])(smem + 158720);   //  16896 B
    __half (*W2s)[264] = (__half(*)[264])(smem + 175616);   //  33792 B

    const int tid  = threadIdx.x;
    const int lane = tid & 31, wid = tid >> 5;
    const int qr   = lane & 3, gr = lane >> 2;
    const int wm0  = (wid >> 3) * 16, wng = wid & 7;
    const int lrow = lane & 15, lkof = (lane >> 4) << 3;
    const int lb   = lane & 7;
    const int m0   = blockIdx.x * 32;

    // ---- loads: Xs (padded), W0 -> Wc buffer 0 (cp.async), W2s ----
    for (int i = tid; i < 32 * MDEN; i += 512) {
        int r = i / MDEN, c = i % MDEN;
        Xs[r][c] = __float2half_rn(dense_x[(size_t)(m0 + r) * MDEN + c]);
    }
    for (int i = tid; i < 32 * (32 - MDEN); i += 512) {
        int r = i / (32 - MDEN), c = MDEN + i % (32 - MDEN);
        Xs[r][c] = __float2half_rn(0.f);
    }
    #pragma unroll
    for (int j = 0; j < 4; j++) {                    // W0: 512 rows x 32 k
        int f = tid + j * 512, r = f >> 2, c = (f & 3) * 8;
        cp16(smem_u32(Wc + r * BROW + c), W0h + r * 32 + c);
    }
    CP_COMMIT();
    #pragma unroll
    for (int j = 0; j < 4; j++) {                    // W2s: 64x256 halves
        int f = tid + j * 512, r = f >> 5, c = (f & 31) * 8;
        *(uint4*)&W2s[r][c] = *(const uint4*)&W2h[r * 256 + c];
    }
    asm volatile("cp.async.wait_group 0;" ::: "memory");
    __syncthreads();

    // ---- stage A: K=32 resident, out 32x512 -> H1s (relu) ----
    mlp_stage<32, 512, 40, 520, true>(&Xs[0][0], Wc, nullptr, bb0, &H1s[0][0]);
    __syncthreads();

    // ---- stage B: K=512 streamed (warp-private), out 32x256 -> H2s (relu) ----
    mlp_stage<512, 256, 520, 264, false>(&H1s[0][0], Wc, W1h, bb1, &H2s[0][0]);
    __syncthreads();

    // ---- stage C: K=256, out 32x64 -> g_xb fp16 (no relu) ----
    {
        float acc[4];
        #pragma unroll
        for (int e = 0; e < 4; e++) acc[e] = 0.f;
        const int sel1 = (lane >> 3) & 1;
        #pragma unroll 4
        for (int kk = 0; kk < 256; kk += 16) {
            uint32_t af[4], bf[2];
            ldm_x4(af, smem_u32(&H2s[wm0 + lrow][kk + lkof]));
            ldm_x2(bf, smem_u32(&W2s[wng * 8 + lb][kk + sel1 * 8]));
            mma_f16(acc, af, bf[0], bf[1]);
        }
        int col = wng * 8 + 2 * qr;
        float bx = bb2[col], by = bb2[col + 1];
        __half2 v0 = __floats2half2_rn(acc[0] + bx, acc[1] + by);
        __half2 v1 = __floats2half2_rn(acc[2] + bx, acc[3] + by);
        *(__half2*)&g_xb[(size_t)(m0 + wm0 + gr) * EMBD + col]     = v0;
        *(__half2*)&g_xb[(size_t)(m0 + wm0 + gr + 8) * EMBD + col] = v1;
    }
}

// ---------------------------------------------------------------------------
// Top MLP megakernel: 32 batch rows / CTA, grid 128, 512 threads.
//   0: gather embeddings + x_bot -> T (fp16, in Wc region), pairwise dots -> Xs
//   A: T1 = relu(Xs @ TW0^T)   B: T2 = relu(T1 @ TW1^T)   C: out = T2.tw2+tb2
// ---------------------------------------------------------------------------
#define TOP_SMEM 206336
#define TPAD 28
__global__ __launch_bounds__(512)
void top_mlp(const int* __restrict__ sidx,
             const float* __restrict__ emb,
             const __half* __restrict__ TW0h,
             const __half* __restrict__ TW1h,
             const float* __restrict__ tb0,
             const float* __restrict__ tb1,
             const float* __restrict__ tw2,
             const float* __restrict__ tb2,
             float* __restrict__ out)
{
    extern __shared__ __align__(16) char smem[];
    __half (*Xs)[520]  = (__half(*)[520])(smem + 0);        //  33280 B
    __half (*H1s)[520] = (__half(*)[520])(smem + 33280);    //  33280 B
    __half* Wc         = (__half*)       (smem + 66560);    // 122880 B (3 bufs)
    __half (*H2s)[264] = (__half(*)[264])(smem + 189440);   //  16896 B
    // T tile overlaps Wc: [32 rows][64 k][28] fp16 = 114688 B <= 122880 B
    __half (*Tw)[EMBD][TPAD] = (__half(*)[EMBD][TPAD])(smem + 66560);

    const int tid  = threadIdx.x;
    const int lane = tid & 31, wid = tid >> 5;
    const int m0   = blockIdx.x * 32;

    // ---- phase 0: gather + interaction (warp w handles rows 2w, 2w+1) ----
    #pragma unroll 1
    for (int rr = 0; rr < 2; rr++) {
        const int r = wid * 2 + rr;
        const int b = m0 + r;

        // x_bot -> Xs[r][0:64] and T row 0
        __half2 xb2 = ((const __half2*)(g_xb + (size_t)b * EMBD))[lane];
        ((__half2*)&Xs[r][0])[lane] = xb2;
        Tw[r][2*lane][0]     = __low2half(xb2);
        Tw[r][2*lane + 1][0] = __high2half(xb2);

        // embeddings, 2 batches of 13 outstanding loads
        #pragma unroll 1
        for (int h = 0; h < 2; h++) {
            const float* srcs[13];
            #pragma unroll
            for (int e = 0; e < 13; e++) {
                int f = h * 13 + e;
                int ix = sidx[(size_t)f * BATCH + b];
                ix = ix < 0 ? 0 : (ix >= VOCAB ? VOCAB - 1 : ix);
                srcs[e] = emb + ((size_t)f * VOCAB + (size_t)ix) * EMBD;
            }
            float2 v[13];
            #pragma unroll
            for (int e = 0; e < 13; e++)
                v[e] = ((const float2*)srcs[e])[lane];
            #pragma unroll
            for (int e = 0; e < 13; e++) {
                int f = h * 13 + e;
                Tw[r][2*lane][f + 1]     = __float2half_rn(v[e].x);
                Tw[r][2*lane + 1][f + 1] = __float2half_rn(v[e].y);
            }
        }
        __syncwarp();

        // pairwise dots (lanes 0..27, 4x4 tile each)
        if (lane < 28) {
            int ti = 0;
            while ((ti + 1) * (ti + 2) / 2 <= lane) ti++;
            int tj = lane - ti * (ti + 1) / 2;

            float acc[4][4];
            #pragma unroll
            for (int a = 0; a < 4; a++)
                #pragma unroll
                for (int c = 0; c < 4; c++)
                    acc[a][c] = 0.f;

            #pragma unroll 8
            for (int k = 0; k < EMBD; k++) {
                __half2 a01 = *(const __half2*)&Tw[r][k][4*ti];
                __half2 a23 = *(const __half2*)&Tw[r][k][4*ti + 2];
                __half2 b01 = *(const __half2*)&Tw[r][k][4*tj];
                __half2 b23 = *(const __half2*)&Tw[r][k][4*tj + 2];
                float2 fa01 = __half22float2(a01), fa23 = __half22float2(a23);
                float2 fb01 = __half22float2(b01), fb23 = __half22float2(b23);
                float ra[4] = {fa01.x, fa01.y, fa23.x, fa23.y};
                float rb[4] = {fb01.x, fb01.y, fb23.x, fb23.y};
                #pragma unroll
                for (int a = 0; a < 4; a++)
                    #pragma unroll
                    for (int c = 0; c < 4; c++)
                        acc[a][c] += ra[a] * rb[c];
            }

            #pragma unroll
            for (int a = 0; a < 4; a++) {
                int i = 4*ti + a;
                #pragma unroll
                for (int c = 0; c < 4; c++) {
                    int j = 4*tj + c;
                    if (i < NI && j < i)
                        Xs[r][EMBD + i*(i-1)/2 + j] = __float2half_rn(acc[a][c]);
                }
            }
        }
        __syncwarp();
    }

    // zero pad cols [415, 512)
    for (int i = tid; i < 32 * (PDIM - TOPIN); i += 512) {
        int r = i / (PDIM - TOPIN), c = TOPIN + i % (PDIM - TOPIN);
        Xs[r][c] = __float2half_rn(0.f);
    }
    __syncthreads();

    mlp_stage<512, 512, 520, 520, false>(&Xs[0][0], Wc, TW0h, tb0, &H1s[0][0]);
    __syncthreads();
    mlp_stage<512, 256, 520, 264, false>(&H1s[0][0], Wc, TW1h, tb1, &H2s[0][0]);
    __syncthreads();

    // final dot: 16 threads per row (H2s already holds relu(T2))
    {
        int r = tid >> 4, part = tid & 15;
        float s = 0.f;
        #pragma unroll
        for (int c = 0; c < 16; c++) {
            int col = part * 16 + c;
            s += __half2float(H2s[r][col]) * tw2[col];
        }
        s += __shfl_xor_sync(0xffffffffu, s, 1);
        s += __shfl_xor_sync(0xffffffffu, s, 2);
        s += __shfl_xor_sync(0xffffffffu, s, 4);
        s += __shfl_xor_sync(0xffffffffu, s, 8);
        if (part == 0) out[m0 + r] = s + tb2[0];
    }
}

// ---------------------------------------------------------------------------
// Launch sequence
// ---------------------------------------------------------------------------
extern "C" void kernel_launch(void* const* d_in, const int* in_sizes, int n_in,
                              void* d_out, int out_size)
{
    const float* dense_x = (const float*)d_in[0];
    const int*   sidx    = (const int*)d_in[1];
    const float* emb     = (const float*)d_in[2];
    const float* bw0 = (const float*)d_in[3];
    const float* bb0 = (const float*)d_in[4];
    const float* bw1 = (const float*)d_in[5];
    const float* bb1 = (const float*)d_in[6];
    const float* bw2 = (const float*)d_in[7];
    const float* bb2 = (const float*)d_in[8];
    const float* tw0 = (const float*)d_in[9];
    const float* tb0 = (const float*)d_in[10];
    const float* tw1 = (const float*)d_in[11];
    const float* tb1 = (const float*)d_in[12];
    const float* tw2 = (const float*)d_in[13];
    const float* tb2 = (const float*)d_in[14];
    float* out = (float*)d_out;

    __half* wh;
    cudaGetSymbolAddress((void**)&wh, g_wh);

    cudaFuncSetAttribute(bottom_mlp, cudaFuncAttributeMaxDynamicSharedMemorySize, BOT_SMEM);
    cudaFuncSetAttribute(top_mlp,    cudaFuncAttributeMaxDynamicSharedMemorySize, TOP_SMEM);

    prep_kernel<<<256, 256>>>(bw0, bw1, bw2, tw0, tw1);

    bottom_mlp<<<BATCH/32, 512, BOT_SMEM>>>(dense_x, wh + HW0, wh + HW1, wh + HW2,
                                            bb0, bb1, bb2);

    top_mlp<<<BATCH/32, 512, TOP_SMEM>>>(sidx, emb, wh + HTW0, wh + HTW1,
                                         tb0, tb1, tw2, tb2, out);
}

// round 16
// speedup vs baseline: 1.1072x; 1.0294x over previous
#include <cuda_runtime.h>
#include <cuda_fp16.h>
#include <cstdint>
#include <math.h>

// ---------------------------------------------------------------------------
// DLRM forward, 3 launches:
//   prep -> bottom_mlp (fused 3-layer) -> top_mlp (gather+interact+3-layer)
// mma.sync m16n8k16 fp16 (fp32 accum). 512 threads / 16 warps per CTA.
// Streamed stages: warp-private cp.async pipeline (no CTA barriers in loop).
// ---------------------------------------------------------------------------

#define BATCH   4096
#define MDEN    13
#define NI      27
#define EMBD    64
#define VOCAB   100000
#define TOPIN   415
#define PDIM    512

// compact bottom output: x_bot fp16 [4096, 64]
__device__ __align__(16) __half g_xb[BATCH * EMBD];

// fp16 weights
#define HW0   0                     // [512,32]  (bw0 zero-padded 13->32)
#define HW1   (HW0  + 512*32)       // [256,512]
#define HW2   (HW1  + 256*512)      // [64,256]
#define HTW0  (HW2  + 64*256)       // [512,512] (tw0 zero-padded 415->512)
#define HTW1  (HTW0 + 512*512)      // [256,512]
#define HTOTAL (HTW1 + 256*512)
__device__ __align__(16) __half g_wh[HTOTAL];

#define BROW    40                  // halves per smem weight row (32 + 8 pad)
#define BUFH    (512*BROW)          // halves per weight buffer

__device__ __forceinline__ uint32_t smem_u32(const void* p) {
    uint32_t a;
    asm("{ .reg .u64 t; cvta.to.shared.u64 t, %1; cvt.u32.u64 %0, t; }"
        : "=r"(a) : "l"(p));
    return a;
}
__device__ __forceinline__ void mma_f16(float* c, const uint32_t* a,
                                        uint32_t b0, uint32_t b1) {
    asm volatile(
        "mma.sync.aligned.m16n8k16.row.col.f32.f16.f16.f32 "
        "{%0,%1,%2,%3}, {%4,%5,%6,%7}, {%8,%9}, {%0,%1,%2,%3};"
        : "+f"(c[0]), "+f"(c[1]), "+f"(c[2]), "+f"(c[3])
        : "r"(a[0]), "r"(a[1]), "r"(a[2]), "r"(a[3]), "r"(b0), "r"(b1));
}
__device__ __forceinline__ void ldm_x4(uint32_t* r, uint32_t addr) {
    asm volatile("ldmatrix.sync.aligned.m8n8.x4.shared.b16 {%0,%1,%2,%3}, [%4];"
                 : "=r"(r[0]), "=r"(r[1]), "=r"(r[2]), "=r"(r[3]) : "r"(addr));
}
__device__ __forceinline__ void ldm_x2(uint32_t* r, uint32_t addr) {
    asm volatile("ldmatrix.sync.aligned.m8n8.x2.shared.b16 {%0,%1}, [%2];"
                 : "=r"(r[0]), "=r"(r[1]) : "r"(addr));
}
__device__ __forceinline__ void cp16(uint32_t saddr, const void* g) {
    asm volatile("cp.async.cg.shared.global [%0], [%1], 16;" :: "r"(saddr), "l"(g));
}
#define CP_COMMIT() asm volatile("cp.async.commit_group;" ::: "memory")

// ---------------------------------------------------------------------------
// Prep: convert/pad weights to fp16. Vectorized (float4 -> 2x half2) for the
// flat tables; scalar only for the two padded tables. Grid 1024 x 256.
// ---------------------------------------------------------------------------
__global__ void prep_kernel(const float* __restrict__ bw0,
                            const float* __restrict__ bw1,
                            const float* __restrict__ bw2,
                            const float* __restrict__ tw0,
                            const float* __restrict__ tw1)
{
    int tid = blockIdx.x * blockDim.x + threadIdx.x;
    int stride = gridDim.x * blockDim.x;

    // bw1 [256*512] flat, vectorized
    for (int i = tid; i < 256 * 512 / 4; i += stride) {
        float4 v = ((const float4*)bw1)[i];
        *(__half2*)&g_wh[HW1 + i*4]     = __floats2half2_rn(v.x, v.y);
        *(__half2*)&g_wh[HW1 + i*4 + 2] = __floats2half2_rn(v.z, v.w);
    }
    // tw1 [256*512] flat, vectorized
    for (int i = tid; i < 256 * 512 / 4; i += stride) {
        float4 v = ((const float4*)tw1)[i];
        *(__half2*)&g_wh[HTW1 + i*4]     = __floats2half2_rn(v.x, v.y);
        *(__half2*)&g_wh[HTW1 + i*4 + 2] = __floats2half2_rn(v.z, v.w);
    }
    // bw2 [64*256] flat, vectorized
    for (int i = tid; i < 64 * 256 / 4; i += stride) {
        float4 v = ((const float4*)bw2)[i];
        *(__half2*)&g_wh[HW2 + i*4]     = __floats2half2_rn(v.x, v.y);
        *(__half2*)&g_wh[HW2 + i*4 + 2] = __floats2half2_rn(v.z, v.w);
    }
    // bw0 [512,13] -> [512,32] zero-padded (scalar, small)
    for (int i = tid; i < 512 * 32; i += stride) {
        int r = i >> 5, c = i & 31;
        g_wh[HW0 + i] = __float2half_rn((c < MDEN) ? bw0[r * MDEN + c] : 0.f);
    }
    // tw0 [512,415] -> [512,512] zero-padded (scalar, ~1 elem/thread)
    for (int i = tid; i < 512 * PDIM; i += stride) {
        int r = i >> 9, c = i & 511;
        g_wh[HTW0 + i] = __float2half_rn((c < TOPIN) ? tw0[r * TOPIN + c] : 0.f);
    }
}

// ---------------------------------------------------------------------------
// MLP stage (512 threads / 16 warps):
//   Ds[32][NOUT] = relu( As[32][K_TOT] @ W[NOUT,K_TOT]^T + bias )
// Warp w owns n-cols [w*NW, (w+1)*NW), NW = NOUT/16, full m=32.
// RESIDENT: weights already in Wc buffer 0. Streamed: warp-private cp.async
// pipeline (each warp loads only its own NW rows of each [NOUT x 32k] chunk;
// 3 buffers, 2 chunks in flight, no __syncthreads in the loop).
// ---------------------------------------------------------------------------
template<int K_TOT, int NOUT, int ASTRIDE, int DSTRIDE, bool RESIDENT>
__device__ __forceinline__ void mlp_stage(
    const __half* As, __half* Wc, const __half* Wg,
    const float* bias, __half* Ds)
{
    constexpr int NC = K_TOT / 32;
    constexpr int NW = NOUT / 16;     // n-cols per warp (16 or 32)
    constexpr int NT = NW / 8;        // n8 tiles per warp (2 or 4)
    constexpr int NP = (NW + 15) / 16;// ldm_x4 B loads per kstep (1 or 2)
    constexpr int CPI = NW / 8;       // cp16 per thread per chunk

    const int tid  = threadIdx.x;
    const int lane = tid & 31, wid = tid >> 5;
    const int qr   = lane & 3, gr = lane >> 2;
    const int lrow = lane & 15, lkof = (lane >> 4) << 3;
    const int lb   = lane & 7,  sel  = lane >> 3;
    const int bko  = (sel & 1) << 3;
    const int brow = wid * NW + ((sel & 2) << 2) + lb;

    auto issue = [&](int g) {
        const __half* src = Wg + g * 32;
        __half* buf = Wc + (g % 3) * BUFH;
        #pragma unroll
        for (int j = 0; j < CPI; j++) {
            int f = j * 32 + lane;
            int r = wid * NW + (f >> 2);
            int c = (f & 3) * 8;
            cp16(smem_u32(buf + r * BROW + c), src + (size_t)r * K_TOT + c);
        }
        CP_COMMIT();
    };

    if (!RESIDENT) {
        issue(0);
        if (NC > 1) issue(1);
    }

    float acc[2][NT][4];
    #pragma unroll
    for (int mt = 0; mt < 2; mt++)
        #pragma unroll
        for (int j = 0; j < NT; j++)
            #pragma unroll
            for (int e = 0; e < 4; e++)
                acc[mt][j][e] = 0.f;

    #pragma unroll 1
    for (int g = 0; g < NC; g++) {
        if (!RESIDENT) {
            if (g < NC - 1) asm volatile("cp.async.wait_group 1;" ::: "memory");
            else            asm volatile("cp.async.wait_group 0;" ::: "memory");
        }
        const __half* Wb = Wc + (RESIDENT ? 0 : (g % 3)) * BUFH;

        #pragma unroll
        for (int kk = 0; kk < 32; kk += 16) {
            uint32_t a0[4], a1[4];
            ldm_x4(a0, smem_u32(As + (size_t)lrow * ASTRIDE + g * 32 + kk + lkof));
            ldm_x4(a1, smem_u32(As + (size_t)(16 + lrow) * ASTRIDE + g * 32 + kk + lkof));
            #pragma unroll
            for (int p = 0; p < NP; p++) {
                uint32_t bf[4];
                ldm_x4(bf, smem_u32(Wb + (size_t)(brow + p * 16) * BROW + kk + bko));
                mma_f16(acc[0][2*p + 0], a0, bf[0], bf[1]);
                mma_f16(acc[0][2*p + 1], a0, bf[2], bf[3]);
                mma_f16(acc[1][2*p + 0], a1, bf[0], bf[1]);
                mma_f16(acc[1][2*p + 1], a1, bf[2], bf[3]);
            }
        }

        if (!RESIDENT && g + 2 < NC) issue(g + 2);
    }

    // epilogue: bias + relu -> Ds (fp16)
    #pragma unroll
    for (int mt = 0; mt < 2; mt++) {
        #pragma unroll
        for (int j = 0; j < NT; j++) {
            int col = wid * NW + j * 8 + 2 * qr;
            float bx = bias[col], by = bias[col + 1];
            float v0 = fmaxf(acc[mt][j][0] + bx, 0.f), v1 = fmaxf(acc[mt][j][1] + by, 0.f);
            float v2 = fmaxf(acc[mt][j][2] + bx, 0.f), v3 = fmaxf(acc[mt][j][3] + by, 0.f);
            int r0 = mt * 16 + gr;
            *(__half2*)&Ds[(size_t)r0 * DSTRIDE + col]       = __floats2half2_rn(v0, v1);
            *(__half2*)&Ds[(size_t)(r0 + 8) * DSTRIDE + col] = __floats2half2_rn(v2, v3);
        }
    }
}

// ---------------------------------------------------------------------------
// Bottom MLP megakernel: 32 batch rows / CTA, grid 128, 512 threads.
//   A: H1 = relu(dense @ W0^T)   B: H2 = relu(H1 @ W1^T)   C: x_bot -> g_xb
// ---------------------------------------------------------------------------
#define BOT_SMEM 209408
__global__ __launch_bounds__(512)
void bottom_mlp(const float* __restrict__ dense_x,
                const __half* __restrict__ W0h,
                const __half* __restrict__ W1h,
                const __half* __restrict__ W2h,
                const float* __restrict__ bb0,
                const float* __restrict__ bb1,
                const float* __restrict__ bb2)
{
    extern __shared__ __align__(16) char smem[];
    __half (*Xs)[40]   = (__half(*)[40] )(smem + 0);        //   2560 B
    __half (*H1s)[520] = (__half(*)[520])(smem + 2560);     //  33280 B
    __half* Wc         = (__half*)       (smem + 35840);    // 122880 B (3 bufs)
    __half (*H2s)[264] = (__half(*)[264])(smem + 158720);   //  16896 B
    __half (*W2s)[264] = (__half(*)[264])(smem + 175616);   //  33792 B

    const int tid  = threadIdx.x;
    const int lane = tid & 31, wid = tid >> 5;
    const int qr   = lane & 3, gr = lane >> 2;
    const int wm0  = (wid >> 3) * 16, wng = wid & 7;
    const int lrow = lane & 15, lkof = (lane >> 4) << 3;
    const int lb   = lane & 7;
    const int m0   = blockIdx.x * 32;

    // ---- loads: Xs (padded), W0 -> Wc buffer 0 (cp.async), W2s ----
    for (int i = tid; i < 32 * MDEN; i += 512) {
        int r = i / MDEN, c = i % MDEN;
        Xs[r][c] = __float2half_rn(dense_x[(size_t)(m0 + r) * MDEN + c]);
    }
    for (int i = tid; i < 32 * (32 - MDEN); i += 512) {
        int r = i / (32 - MDEN), c = MDEN + i % (32 - MDEN);
        Xs[r][c] = __float2half_rn(0.f);
    }
    #pragma unroll
    for (int j = 0; j < 4; j++) {                    // W0: 512 rows x 32 k
        int f = tid + j * 512, r = f >> 2, c = (f & 3) * 8;
        cp16(smem_u32(Wc + r * BROW + c), W0h + r * 32 + c);
    }
    CP_COMMIT();
    #pragma unroll
    for (int j = 0; j < 4; j++) {                    // W2s: 64x256 halves
        int f = tid + j * 512, r = f >> 5, c = (f & 31) * 8;
        *(uint4*)&W2s[r][c] = *(const uint4*)&W2h[r * 256 + c];
    }
    asm volatile("cp.async.wait_group 0;" ::: "memory");
    __syncthreads();

    // ---- stage A: K=32 resident, out 32x512 -> H1s (relu) ----
    mlp_stage<32, 512, 40, 520, true>(&Xs[0][0], Wc, nullptr, bb0, &H1s[0][0]);
    __syncthreads();

    // ---- stage B: K=512 streamed (warp-private), out 32x256 -> H2s (relu) ----
    mlp_stage<512, 256, 520, 264, false>(&H1s[0][0], Wc, W1h, bb1, &H2s[0][0]);
    __syncthreads();

    // ---- stage C: K=256, out 32x64 -> g_xb fp16 (no relu) ----
    {
        float acc[4];
        #pragma unroll
        for (int e = 0; e < 4; e++) acc[e] = 0.f;
        const int sel1 = (lane >> 3) & 1;
        #pragma unroll 4
        for (int kk = 0; kk < 256; kk += 16) {
            uint32_t af[4], bf[2];
            ldm_x4(af, smem_u32(&H2s[wm0 + lrow][kk + lkof]));
            ldm_x2(bf, smem_u32(&W2s[wng * 8 + lb][kk + sel1 * 8]));
            mma_f16(acc, af, bf[0], bf[1]);
        }
        int col = wng * 8 + 2 * qr;
        float bx = bb2[col], by = bb2[col + 1];
        __half2 v0 = __floats2half2_rn(acc[0] + bx, acc[1] + by);
        __half2 v1 = __floats2half2_rn(acc[2] + bx, acc[3] + by);
        *(__half2*)&g_xb[(size_t)(m0 + wm0 + gr) * EMBD + col]     = v0;
        *(__half2*)&g_xb[(size_t)(m0 + wm0 + gr + 8) * EMBD + col] = v1;
    }
}

// ---------------------------------------------------------------------------
// Top MLP megakernel: 32 batch rows / CTA, grid 128, 512 threads.
//   0: gather embeddings + x_bot -> T (fp16, in Wc region), pairwise dots -> Xs
//   A: T1 = relu(Xs @ TW0^T)   B: T2 = relu(T1 @ TW1^T)   C: out = T2.tw2+tb2
// ---------------------------------------------------------------------------
#define TOP_SMEM 206336
#define TPAD 28
__global__ __launch_bounds__(512)
void top_mlp(const int* __restrict__ sidx,
             const float* __restrict__ emb,
             const __half* __restrict__ TW0h,
             const __half* __restrict__ TW1h,
             const float* __restrict__ tb0,
             const float* __restrict__ tb1,
             const float* __restrict__ tw2,
             const float* __restrict__ tb2,
             float* __restrict__ out)
{
    extern __shared__ __align__(16) char smem[];
    __half (*Xs)[520]  = (__half(*)[520])(smem + 0);        //  33280 B
    __half (*H1s)[520] = (__half(*)[520])(smem + 33280);    //  33280 B
    __half* Wc         = (__half*)       (smem + 66560);    // 122880 B (3 bufs)
    __half (*H2s)[264] = (__half(*)[264])(smem + 189440);   //  16896 B
    // T tile overlaps Wc: [32 rows][64 k][28] fp16 = 114688 B <= 122880 B
    __half (*Tw)[EMBD][TPAD] = (__half(*)[EMBD][TPAD])(smem + 66560);

    const int tid  = threadIdx.x;
    const int lane = tid & 31, wid = tid >> 5;
    const int m0   = blockIdx.x * 32;

    // ---- phase 0: gather + interaction (warp w handles rows 2w, 2w+1) ----
    #pragma unroll 1
    for (int rr = 0; rr < 2; rr++) {
        const int r = wid * 2 + rr;
        const int b = m0 + r;

        // x_bot -> Xs[r][0:64] and T row 0
        __half2 xb2 = ((const __half2*)(g_xb + (size_t)b * EMBD))[lane];
        ((__half2*)&Xs[r][0])[lane] = xb2;
        Tw[r][2*lane][0]     = __low2half(xb2);
        Tw[r][2*lane + 1][0] = __high2half(xb2);

        // embeddings, 2 batches of 13 outstanding loads
        #pragma unroll 1
        for (int h = 0; h < 2; h++) {
            const float* srcs[13];
            #pragma unroll
            for (int e = 0; e < 13; e++) {
                int f = h * 13 + e;
                int ix = sidx[(size_t)f * BATCH + b];
                ix = ix < 0 ? 0 : (ix >= VOCAB ? VOCAB - 1 : ix);
                srcs[e] = emb + ((size_t)f * VOCAB + (size_t)ix) * EMBD;
            }
            float2 v[13];
            #pragma unroll
            for (int e = 0; e < 13; e++)
                v[e] = ((const float2*)srcs[e])[lane];
            #pragma unroll
            for (int e = 0; e < 13; e++) {
                int f = h * 13 + e;
                Tw[r][2*lane][f + 1]     = __float2half_rn(v[e].x);
                Tw[r][2*lane + 1][f + 1] = __float2half_rn(v[e].y);
            }
        }
        __syncwarp();

        // pairwise dots (lanes 0..27, 4x4 tile each)
        if (lane < 28) {
            int ti = 0;
            while ((ti + 1) * (ti + 2) / 2 <= lane) ti++;
            int tj = lane - ti * (ti + 1) / 2;

            float acc[4][4];
            #pragma unroll
            for (int a = 0; a < 4; a++)
                #pragma unroll
                for (int c = 0; c < 4; c++)
                    acc[a][c] = 0.f;

            #pragma unroll 8
            for (int k = 0; k < EMBD; k++) {
                __half2 a01 = *(const __half2*)&Tw[r][k][4*ti];
                __half2 a23 = *(const __half2*)&Tw[r][k][4*ti + 2];
                __half2 b01 = *(const __half2*)&Tw[r][k][4*tj];
                __half2 b23 = *(const __half2*)&Tw[r][k][4*tj + 2];
                float2 fa01 = __half22float2(a01), fa23 = __half22float2(a23);
                float2 fb01 = __half22float2(b01), fb23 = __half22float2(b23);
                float ra[4] = {fa01.x, fa01.y, fa23.x, fa23.y};
                float rb[4] = {fb01.x, fb01.y, fb23.x, fb23.y};
                #pragma unroll
                for (int a = 0; a < 4; a++)
                    #pragma unroll
                    for (int c = 0; c < 4; c++)
                        acc[a][c] += ra[a] * rb[c];
            }

            #pragma unroll
            for (int a = 0; a < 4; a++) {
                int i = 4*ti + a;
                #pragma unroll
                for (int c = 0; c < 4; c++) {
                    int j = 4*tj + c;
                    if (i < NI && j < i)
                        Xs[r][EMBD + i*(i-1)/2 + j] = __float2half_rn(acc[a][c]);
                }
            }
        }
        __syncwarp();
    }

    // zero pad cols [415, 512)
    for (int i = tid; i < 32 * (PDIM - TOPIN); i += 512) {
        int r = i / (PDIM - TOPIN), c = TOPIN + i % (PDIM - TOPIN);
        Xs[r][c] = __float2half_rn(0.f);
    }
    __syncthreads();

    mlp_stage<512, 512, 520, 520, false>(&Xs[0][0], Wc, TW0h, tb0, &H1s[0][0]);
    __syncthreads();
    mlp_stage<512, 256, 520, 264, false>(&H1s[0][0], Wc, TW1h, tb1, &H2s[0][0]);
    __syncthreads();

    // final dot: 16 threads per row (H2s already holds relu(T2))
    {
        int r = tid >> 4, part = tid & 15;
        float s = 0.f;
        #pragma unroll
        for (int c = 0; c < 16; c++) {
            int col = part * 16 + c;
            s += __half2float(H2s[r][col]) * tw2[col];
        }
        s += __shfl_xor_sync(0xffffffffu, s, 1);
        s += __shfl_xor_sync(0xffffffffu, s, 2);
        s += __shfl_xor_sync(0xffffffffu, s, 4);
        s += __shfl_xor_sync(0xffffffffu, s, 8);
        if (part == 0) out[m0 + r] = s + tb2[0];
    }
}

// ---------------------------------------------------------------------------
// Launch sequence
// ---------------------------------------------------------------------------
extern "C" void kernel_launch(void* const* d_in, const int* in_sizes, int n_in,
                              void* d_out, int out_size)
{
    const float* dense_x = (const float*)d_in[0];
    const int*   sidx    = (const int*)d_in[1];
    const float* emb     = (const float*)d_in[2];
    const float* bw0 = (const float*)d_in[3];
    const float* bb0 = (const float*)d_in[4];
    const float* bw1 = (const float*)d_in[5];
    const float* bb1 = (const float*)d_in[6];
    const float* bw2 = (const float*)d_in[7];
    const float* bb2 = (const float*)d_in[8];
    const float* tw0 = (const float*)d_in[9];
    const float* tb0 = (const float*)d_in[10];
    const float* tw1 = (const float*)d_in[11];
    const float* tb1 = (const float*)d_in[12];
    const float* tw2 = (const float*)d_in[13];
    const float* tb2 = (const float*)d_in[14];
    float* out = (float*)d_out;

    __half* wh;
    cudaGetSymbolAddress((void**)&wh, g_wh);

    cudaFuncSetAttribute(bottom_mlp, cudaFuncAttributeMaxDynamicSharedMemorySize, BOT_SMEM);
    cudaFuncSetAttribute(top_mlp,    cudaFuncAttributeMaxDynamicSharedMemorySize, TOP_SMEM);

    prep_kernel<<<1024, 256>>>(bw0, bw1, bw2, tw0, tw1);

    bottom_mlp<<<BATCH/32, 512, BOT_SMEM>>>(dense_x, wh + HW0, wh + HW1, wh + HW2,
                                            bb0, bb1, bb2);

    top_mlp<<<BATCH/32, 512, TOP_SMEM>>>(sidx, emb, wh + HTW0, wh + HTW1,
                                         tb0, tb1, tw2, tb2, out);
}

// round 17
// speedup vs baseline: 1.1238x; 1.0149x over previous
#include <cuda_runtime.h>
#include <cuda_fp16.h>
#include <cstdint>
#include <math.h>

// ---------------------------------------------------------------------------
// DLRM forward, 3 launches:
//   prep -> bottom_mlp (fused 3-layer) -> top_mlp (gather+interact+3-layer)
// mma.sync m16n8k16 fp16 (fp32 accum). 512 threads / 16 warps per CTA.
// Streamed stages: warp-private cp.async pipeline (no CTA barriers in loop).
// Top-L0 K padded to 416 (not 512): 19% less weight streaming.
// ---------------------------------------------------------------------------

#define BATCH   4096
#define MDEN    13
#define NI      27
#define EMBD    64
#define VOCAB   100000
#define TOPIN   415
#define TKP     416      // top-L0 K padded to multiple of 32

// compact bottom output: x_bot fp16 [4096, 64]
__device__ __align__(16) __half g_xb[BATCH * EMBD];

// fp16 weights
#define HW0   0                     // [512,32]  (bw0 zero-padded 13->32)
#define HW1   (HW0  + 512*32)       // [256,512]
#define HW2   (HW1  + 256*512)      // [64,256]
#define HTW0  (HW2  + 64*256)       // [512,416] (tw0 zero-padded 415->416)
#define HTW1  (HTW0 + 512*TKP)      // [256,512]
#define HTOTAL (HTW1 + 256*512)
__device__ __align__(16) __half g_wh[HTOTAL];

#define BROW    40                  // halves per smem weight row (32 + 8 pad)
#define BUFH    (512*BROW)          // halves per weight buffer

__device__ __forceinline__ uint32_t smem_u32(const void* p) {
    uint32_t a;
    asm("{ .reg .u64 t; cvta.to.shared.u64 t, %1; cvt.u32.u64 %0, t; }"
        : "=r"(a) : "l"(p));
    return a;
}
__device__ __forceinline__ void mma_f16(float* c, const uint32_t* a,
                                        uint32_t b0, uint32_t b1) {
    asm volatile(
        "mma.sync.aligned.m16n8k16.row.col.f32.f16.f16.f32 "
        "{%0,%1,%2,%3}, {%4,%5,%6,%7}, {%8,%9}, {%0,%1,%2,%3};"
        : "+f"(c[0]), "+f"(c[1]), "+f"(c[2]), "+f"(c[3])
        : "r"(a[0]), "r"(a[1]), "r"(a[2]), "r"(a[3]), "r"(b0), "r"(b1));
}
__device__ __forceinline__ void ldm_x4(uint32_t* r, uint32_t addr) {
    asm volatile("ldmatrix.sync.aligned.m8n8.x4.shared.b16 {%0,%1,%2,%3}, [%4];"
                 : "=r"(r[0]), "=r"(r[1]), "=r"(r[2]), "=r"(r[3]) : "r"(addr));
}
__device__ __forceinline__ void ldm_x2(uint32_t* r, uint32_t addr) {
    asm volatile("ldmatrix.sync.aligned.m8n8.x2.shared.b16 {%0,%1}, [%2];"
                 : "=r"(r[0]), "=r"(r[1]) : "r"(addr));
}
__device__ __forceinline__ void cp16(uint32_t saddr, const void* g) {
    asm volatile("cp.async.cg.shared.global [%0], [%1], 16;" :: "r"(saddr), "l"(g));
}
#define CP_COMMIT() asm volatile("cp.async.commit_group;" ::: "memory")

// ---------------------------------------------------------------------------
// Prep: convert/pad weights to fp16. Work partitioned by BLOCK RANGE so the
// five sections run concurrently (no per-thread serial loop chain).
// Grid 1024 x 256.
// ---------------------------------------------------------------------------
__global__ void prep_kernel(const float* __restrict__ bw0,
                            const float* __restrict__ bw1,
                            const float* __restrict__ bw2,
                            const float* __restrict__ tw0,
                            const float* __restrict__ tw1)
{
    const int blk = blockIdx.x;

    if (blk < 832) {
        // tw0 [512,415] -> [512,416] zero-padded: 212992 elems, 1/thread
        int i = blk * 256 + threadIdx.x;            // dst index in [0, 512*416)
        if (i < 512 * TKP) {
            int r = i / TKP, c = i - r * TKP;
            g_wh[HTW0 + i] = __float2half_rn((c < TOPIN) ? tw0[r * TOPIN + c] : 0.f);
        }
    } else if (blk < 896) {
        // tw1 [256*512] flat, vectorized: 32768 f4 / 16384 thr = 2/thread
        int base = (blk - 832) * 256 + threadIdx.x;
        #pragma unroll
        for (int j = 0; j < 2; j++) {
            int i = base + j * 16384;
            float4 v = ((const float4*)tw1)[i];
            *(__half2*)&g_wh[HTW1 + i*4]     = __floats2half2_rn(v.x, v.y);
            *(__half2*)&g_wh[HTW1 + i*4 + 2] = __floats2half2_rn(v.z, v.w);
        }
    } else if (blk < 960) {
        // bw1 [256*512] flat, vectorized: 2/thread
        int base = (blk - 896) * 256 + threadIdx.x;
        #pragma unroll
        for (int j = 0; j < 2; j++) {
            int i = base + j * 16384;
            float4 v = ((const float4*)bw1)[i];
            *(__half2*)&g_wh[HW1 + i*4]     = __floats2half2_rn(v.x, v.y);
            *(__half2*)&g_wh[HW1 + i*4 + 2] = __floats2half2_rn(v.z, v.w);
        }
    } else if (blk < 976) {
        // bw2 [64*256] flat, vectorized: 4096 f4 / 4096 thr = 1/thread
        int i = (blk - 960) * 256 + threadIdx.x;
        float4 v = ((const float4*)bw2)[i];
        *(__half2*)&g_wh[HW2 + i*4]     = __floats2half2_rn(v.x, v.y);
        *(__half2*)&g_wh[HW2 + i*4 + 2] = __floats2half2_rn(v.z, v.w);
    } else if (blk < 1040) {
        // bw0 [512,13] -> [512,32] zero-padded: 16384 elems, 1/thread
        int i = (blk - 976) * 256 + threadIdx.x;
        if (i < 512 * 32) {
            int r = i >> 5, c = i & 31;
            g_wh[HW0 + i] = __float2half_rn((c < MDEN) ? bw0[r * MDEN + c] : 0.f);
        }
    }
}

// ---------------------------------------------------------------------------
// MLP stage (512 threads / 16 warps):
//   Ds[32][NOUT] = relu( As[32][K_TOT] @ W[NOUT,K_TOT]^T + bias )
// Warp w owns n-cols [w*NW, (w+1)*NW), NW = NOUT/16, full m=32.
// RESIDENT: weights already in Wc buffer 0. Streamed: warp-private cp.async
// pipeline (each warp loads only its own NW rows of each [NOUT x 32k] chunk;
// 3 buffers, 2 chunks in flight, no __syncthreads in the loop).
// ---------------------------------------------------------------------------
template<int K_TOT, int NOUT, int ASTRIDE, int DSTRIDE, bool RESIDENT>
__device__ __forceinline__ void mlp_stage(
    const __half* As, __half* Wc, const __half* Wg,
    const float* bias, __half* Ds)
{
    constexpr int NC = K_TOT / 32;
    constexpr int NW = NOUT / 16;     // n-cols per warp (16 or 32)
    constexpr int NT = NW / 8;        // n8 tiles per warp (2 or 4)
    constexpr int NP = (NW + 15) / 16;// ldm_x4 B loads per kstep (1 or 2)
    constexpr int CPI = NW / 8;       // cp16 per thread per chunk

    const int tid  = threadIdx.x;
    const int lane = tid & 31, wid = tid >> 5;
    const int qr   = lane & 3, gr = lane >> 2;
    const int lrow = lane & 15, lkof = (lane >> 4) << 3;
    const int lb   = lane & 7,  sel  = lane >> 3;
    const int bko  = (sel & 1) << 3;
    const int brow = wid * NW + ((sel & 2) << 2) + lb;

    auto issue = [&](int g) {
        const __half* src = Wg + g * 32;
        __half* buf = Wc + (g % 3) * BUFH;
        #pragma unroll
        for (int j = 0; j < CPI; j++) {
            int f = j * 32 + lane;
            int r = wid * NW + (f >> 2);
            int c = (f & 3) * 8;
            cp16(smem_u32(buf + r * BROW + c), src + (size_t)r * K_TOT + c);
        }
        CP_COMMIT();
    };

    if (!RESIDENT) {
        issue(0);
        if (NC > 1) issue(1);
    }

    float acc[2][NT][4];
    #pragma unroll
    for (int mt = 0; mt < 2; mt++)
        #pragma unroll
        for (int j = 0; j < NT; j++)
            #pragma unroll
            for (int e = 0; e < 4; e++)
                acc[mt][j][e] = 0.f;

    #pragma unroll 1
    for (int g = 0; g < NC; g++) {
        if (!RESIDENT) {
            if (g < NC - 1) asm volatile("cp.async.wait_group 1;" ::: "memory");
            else            asm volatile("cp.async.wait_group 0;" ::: "memory");
        }
        const __half* Wb = Wc + (RESIDENT ? 0 : (g % 3)) * BUFH;

        #pragma unroll
        for (int kk = 0; kk < 32; kk += 16) {
            uint32_t a0[4], a1[4];
            ldm_x4(a0, smem_u32(As + (size_t)lrow * ASTRIDE + g * 32 + kk + lkof));
            ldm_x4(a1, smem_u32(As + (size_t)(16 + lrow) * ASTRIDE + g * 32 + kk + lkof));
            #pragma unroll
            for (int p = 0; p < NP; p++) {
                uint32_t bf[4];
                ldm_x4(bf, smem_u32(Wb + (size_t)(brow + p * 16) * BROW + kk + bko));
                mma_f16(acc[0][2*p + 0], a0, bf[0], bf[1]);
                mma_f16(acc[0][2*p + 1], a0, bf[2], bf[3]);
                mma_f16(acc[1][2*p + 0], a1, bf[0], bf[1]);
                mma_f16(acc[1][2*p + 1], a1, bf[2], bf[3]);
            }
        }

        if (!RESIDENT && g + 2 < NC) issue(g + 2);
    }

    // epilogue: bias + relu -> Ds (fp16)
    #pragma unroll
    for (int mt = 0; mt < 2; mt++) {
        #pragma unroll
        for (int j = 0; j < NT; j++) {
            int col = wid * NW + j * 8 + 2 * qr;
            float bx = bias[col], by = bias[col + 1];
            float v0 = fmaxf(acc[mt][j][0] + bx, 0.f), v1 = fmaxf(acc[mt][j][1] + by, 0.f);
            float v2 = fmaxf(acc[mt][j][2] + bx, 0.f), v3 = fmaxf(acc[mt][j][3] + by, 0.f);
            int r0 = mt * 16 + gr;
            *(__half2*)&Ds[(size_t)r0 * DSTRIDE + col]       = __floats2half2_rn(v0, v1);
            *(__half2*)&Ds[(size_t)(r0 + 8) * DSTRIDE + col] = __floats2half2_rn(v2, v3);
        }
    }
}

// ---------------------------------------------------------------------------
// Bottom MLP megakernel: 32 batch rows / CTA, grid 128, 512 threads.
//   A: H1 = relu(dense @ W0^T)   B: H2 = relu(H1 @ W1^T)   C: x_bot -> g_xb
// ---------------------------------------------------------------------------
#define BOT_SMEM 209408
__global__ __launch_bounds__(512)
void bottom_mlp(const float* __restrict__ dense_x,
                const __half* __restrict__ W0h,
                const __half* __restrict__ W1h,
                const __half* __restrict__ W2h,
                const float* __restrict__ bb0,
                const float* __restrict__ bb1,
                const float* __restrict__ bb2)
{
    extern __shared__ __align__(16) char smem[];
    __half (*Xs)[40]   = (__half(*)[40] )(smem + 0);        //   2560 B
    __half (*H1s)[520] = (__half(*)[520])(smem + 2560);     //  33280 B
    __half* Wc         = (__half*)       (smem + 35840);    // 122880 B (3 bufs)
    __half (*H2s)[264] = (__half(*)[264])(smem + 158720);   //  16896 B
    __half (*W2s)[264] = (__half(*)[264])(smem + 175616);   //  33792 B

    const int tid  = threadIdx.x;
    const int lane = tid & 31, wid = tid >> 5;
    const int qr   = lane & 3, gr = lane >> 2;
    const int wm0  = (wid >> 3) * 16, wng = wid & 7;
    const int lrow = lane & 15, lkof = (lane >> 4) << 3;
    const int lb   = lane & 7;
    const int m0   = blockIdx.x * 32;

    // ---- loads: Xs (padded), W0 -> Wc buffer 0 (cp.async), W2s ----
    for (int i = tid; i < 32 * MDEN; i += 512) {
        int r = i / MDEN, c = i % MDEN;
        Xs[r][c] = __float2half_rn(dense_x[(size_t)(m0 + r) * MDEN + c]);
    }
    for (int i = tid; i < 32 * (32 - MDEN); i += 512) {
        int r = i / (32 - MDEN), c = MDEN + i % (32 - MDEN);
        Xs[r][c] = __float2half_rn(0.f);
    }
    #pragma unroll
    for (int j = 0; j < 4; j++) {                    // W0: 512 rows x 32 k
        int f = tid + j * 512, r = f >> 2, c = (f & 3) * 8;
        cp16(smem_u32(Wc + r * BROW + c), W0h + r * 32 + c);
    }
    CP_COMMIT();
    #pragma unroll
    for (int j = 0; j < 4; j++) {                    // W2s: 64x256 halves
        int f = tid + j * 512, r = f >> 5, c = (f & 31) * 8;
        *(uint4*)&W2s[r][c] = *(const uint4*)&W2h[r * 256 + c];
    }
    asm volatile("cp.async.wait_group 0;" ::: "memory");
    __syncthreads();

    // ---- stage A: K=32 resident, out 32x512 -> H1s (relu) ----
    mlp_stage<32, 512, 40, 520, true>(&Xs[0][0], Wc, nullptr, bb0, &H1s[0][0]);
    __syncthreads();

    // ---- stage B: K=512 streamed (warp-private), out 32x256 -> H2s (relu) ----
    mlp_stage<512, 256, 520, 264, false>(&H1s[0][0], Wc, W1h, bb1, &H2s[0][0]);
    __syncthreads();

    // ---- stage C: K=256, out 32x64 -> g_xb fp16 (no relu) ----
    {
        float acc[4];
        #pragma unroll
        for (int e = 0; e < 4; e++) acc[e] = 0.f;
        const int sel1 = (lane >> 3) & 1;
        #pragma unroll 4
        for (int kk = 0; kk < 256; kk += 16) {
            uint32_t af[4], bf[2];
            ldm_x4(af, smem_u32(&H2s[wm0 + lrow][kk + lkof]));
            ldm_x2(bf, smem_u32(&W2s[wng * 8 + lb][kk + sel1 * 8]));
            mma_f16(acc, af, bf[0], bf[1]);
        }
        int col = wng * 8 + 2 * qr;
        float bx = bb2[col], by = bb2[col + 1];
        __half2 v0 = __floats2half2_rn(acc[0] + bx, acc[1] + by);
        __half2 v1 = __floats2half2_rn(acc[2] + bx, acc[3] + by);
        *(__half2*)&g_xb[(size_t)(m0 + wm0 + gr) * EMBD + col]     = v0;
        *(__half2*)&g_xb[(size_t)(m0 + wm0 + gr + 8) * EMBD + col] = v1;
    }
}

// ---------------------------------------------------------------------------
// Top MLP megakernel: 32 batch rows / CTA, grid 128, 512 threads.
//   0: gather embeddings + x_bot -> T (fp16, in Wc region), pairwise dots -> Xs
//   A: T1 = relu(Xs @ TW0^T)  (K=416)   B: T2 = relu(T1 @ TW1^T)  (K=512)
//   C: out = T2.tw2 + tb2
// ---------------------------------------------------------------------------
#define XS_STRIDE 424               // 416 + 8 pad (848 B rows: conflict-free)
#define TOP_SMEM  200192
#define TPAD 28
__global__ __launch_bounds__(512)
void top_mlp(const int* __restrict__ sidx,
             const float* __restrict__ emb,
             const __half* __restrict__ TW0h,
             const __half* __restrict__ TW1h,
             const float* __restrict__ tb0,
             const float* __restrict__ tb1,
             const float* __restrict__ tw2,
             const float* __restrict__ tb2,
             float* __restrict__ out)
{
    extern __shared__ __align__(16) char smem[];
    __half (*Xs)[XS_STRIDE] = (__half(*)[XS_STRIDE])(smem + 0);  //  27136 B
    __half (*H1s)[520] = (__half(*)[520])(smem + 27136);         //  33280 B
    __half* Wc         = (__half*)       (smem + 60416);         // 122880 B (3 bufs)
    __half (*H2s)[264] = (__half(*)[264])(smem + 183296);        //  16896 B
    // T tile overlaps Wc: [32 rows][64 k][28] fp16 = 114688 B <= 122880 B
    __half (*Tw)[EMBD][TPAD] = (__half(*)[EMBD][TPAD])(smem + 60416);

    const int tid  = threadIdx.x;
    const int lane = tid & 31, wid = tid >> 5;
    const int m0   = blockIdx.x * 32;

    // ---- phase 0: gather + interaction (warp w handles rows 2w, 2w+1) ----
    #pragma unroll 1
    for (int rr = 0; rr < 2; rr++) {
        const int r = wid * 2 + rr;
        const int b = m0 + r;

        // x_bot -> Xs[r][0:64] and T row 0
        __half2 xb2 = ((const __half2*)(g_xb + (size_t)b * EMBD))[lane];
        ((__half2*)&Xs[r][0])[lane] = xb2;
        Tw[r][2*lane][0]     = __low2half(xb2);
        Tw[r][2*lane + 1][0] = __high2half(xb2);

        // embeddings, 2 batches of 13 outstanding loads
        #pragma unroll 1
        for (int h = 0; h < 2; h++) {
            const float* srcs[13];
            #pragma unroll
            for (int e = 0; e < 13; e++) {
                int f = h * 13 + e;
                int ix = sidx[(size_t)f * BATCH + b];
                ix = ix < 0 ? 0 : (ix >= VOCAB ? VOCAB - 1 : ix);
                srcs[e] = emb + ((size_t)f * VOCAB + (size_t)ix) * EMBD;
            }
            float2 v[13];
            #pragma unroll
            for (int e = 0; e < 13; e++)
                v[e] = ((const float2*)srcs[e])[lane];
            #pragma unroll
            for (int e = 0; e < 13; e++) {
                int f = h * 13 + e;
                Tw[r][2*lane][f + 1]     = __float2half_rn(v[e].x);
                Tw[r][2*lane + 1][f + 1] = __float2half_rn(v[e].y);
            }
        }
        __syncwarp();

        // pairwise dots (lanes 0..27, 4x4 tile each)
        if (lane < 28) {
            int ti = 0;
            while ((ti + 1) * (ti + 2) / 2 <= lane) ti++;
            int tj = lane - ti * (ti + 1) / 2;

            float acc[4][4];
            #pragma unroll
            for (int a = 0; a < 4; a++)
                #pragma unroll
                for (int c = 0; c < 4; c++)
                    acc[a][c] = 0.f;

            #pragma unroll 8
            for (int k = 0; k < EMBD; k++) {
                __half2 a01 = *(const __half2*)&Tw[r][k][4*ti];
                __half2 a23 = *(const __half2*)&Tw[r][k][4*ti + 2];
                __half2 b01 = *(const __half2*)&Tw[r][k][4*tj];
                __half2 b23 = *(const __half2*)&Tw[r][k][4*tj + 2];
                float2 fa01 = __half22float2(a01), fa23 = __half22float2(a23);
                float2 fb01 = __half22float2(b01), fb23 = __half22float2(b23);
                float ra[4] = {fa01.x, fa01.y, fa23.x, fa23.y};
                float rb[4] = {fb01.x, fb01.y, fb23.x, fb23.y};
                #pragma unroll
                for (int a = 0; a < 4; a++)
                    #pragma unroll
                    for (int c = 0; c < 4; c++)
                        acc[a][c] += ra[a] * rb[c];
            }

            #pragma unroll
            for (int a = 0; a < 4; a++) {
                int i = 4*ti + a;
                #pragma unroll
                for (int c = 0; c < 4; c++) {
                    int j = 4*tj + c;
                    if (i < NI && j < i)
                        Xs[r][EMBD + i*(i-1)/2 + j] = __float2half_rn(acc[a][c]);
                }
            }
        }
        __syncwarp();
    }

    // zero pad col 415 (only pad column with K=416)
    if (tid < 32) Xs[tid][TOPIN] = __float2half_rn(0.f);
    __syncthreads();

    mlp_stage<TKP, 512, XS_STRIDE, 520, false>(&Xs[0][0], Wc, TW0h, tb0, &H1s[0][0]);
    __syncthreads();
    mlp_stage<512, 256, 520, 264, false>(&H1s[0][0], Wc, TW1h, tb1, &H2s[0][0]);
    __syncthreads();

    // final dot: 16 threads per row (H2s already holds relu(T2))
    {
        int r = tid >> 4, part = tid & 15;
        float s = 0.f;
        #pragma unroll
        for (int c = 0; c < 16; c++) {
            int col = part * 16 + c;
            s += __half2float(H2s[r][col]) * tw2[col];
        }
        s += __shfl_xor_sync(0xffffffffu, s, 1);
        s += __shfl_xor_sync(0xffffffffu, s, 2);
        s += __shfl_xor_sync(0xffffffffu, s, 4);
        s += __shfl_xor_sync(0xffffffffu, s, 8);
        if (part == 0) out[m0 + r] = s + tb2[0];
    }
}

// ---------------------------------------------------------------------------
// Launch sequence
// ---------------------------------------------------------------------------
extern "C" void kernel_launch(void* const* d_in, const int* in_sizes, int n_in,
                              void* d_out, int out_size)
{
    const float* dense_x = (const float*)d_in[0];
    const int*   sidx    = (const int*)d_in[1];
    const float* emb     = (const float*)d_in[2];
    const float* bw0 = (const float*)d_in[3];
    const float* bb0 = (const float*)d_in[4];
    const float* bw1 = (const float*)d_in[5];
    const float* bb1 = (const float*)d_in[6];
    const float* bw2 = (const float*)d_in[7];
    const float* bb2 = (const float*)d_in[8];
    const float* tw0 = (const float*)d_in[9];
    const float* tb0 = (const float*)d_in[10];
    const float* tw1 = (const float*)d_in[11];
    const float* tb1 = (const float*)d_in[12];
    const float* tw2 = (const float*)d_in[13];
    const float* tb2 = (const float*)d_in[14];
    float* out = (float*)d_out;

    __half* wh;
    cudaGetSymbolAddress((void**)&wh, g_wh);

    cudaFuncSetAttribute(bottom_mlp, cudaFuncAttributeMaxDynamicSharedMemorySize, BOT_SMEM);
    cudaFuncSetAttribute(top_mlp,    cudaFuncAttributeMaxDynamicSharedMemorySize, TOP_SMEM);

    prep_kernel<<<1040, 256>>>(bw0, bw1, bw2, tw0, tw1);

    bottom_mlp<<<BATCH/32, 512, BOT_SMEM>>>(dense_x, wh + HW0, wh + HW1, wh + HW2,
                                            bb0, bb1, bb2);

    top_mlp<<<BATCH/32, 512, TOP_SMEM>>>(sidx, emb, wh + HTW0, wh + HTW1,
                                         tb0, tb1, tw2, tb2, out);
}